// round 15
// baseline (speedup 1.0000x reference)
#include <cuda_runtime.h>
#include <cuda_bf16.h>
#include <cstdint>

constexpr int Bb  = 64;
constexpr int BSs = 8;
constexpr int Mm  = 512;
constexpr int Dd  = 256;
constexpr float NEG_FILL_F = -10000000000.0f;

constexpr int DEPTH_BF = 3;
constexpr int TSZ     = 8192;
constexpr int BSTAGE  = 4 * TSZ;                       // 32KB per stage
constexpr int DSMEM_BF = DEPTH_BF * BSTAGE;            // 96KB, 2 CTAs/SM
constexpr int DEPTH_NN = 4;
constexpr int BK32   = 16;
constexpr int BNNP   = 136;
constexpr int ASTG32   = 128 * BK32;
constexpr int BSTG_NN  = BK32 * BNNP;
constexpr int DSMEM_NN = DEPTH_NN * (ASTG32 + BSTG_NN) * 4;  // 67584 B

// ---------------- scratch ------------------------------------------------------
__device__ __nv_bfloat16 g_x2[(size_t)Bb * Mm * 2 * Dd];
__device__ __nv_bfloat16 g_y2[(size_t)BSs * Mm * 2 * Dd];
__device__ __nv_bfloat16 g_W2[3][(size_t)Dd * 2 * Dd];
__device__ __nv_bfloat16 g_Qx2[(size_t)Bb * Mm * 2 * Dd];
__device__ __nv_bfloat16 g_Kx2[(size_t)Bb * Mm * 2 * Dd];
__device__ __nv_bfloat16 g_Qy2[(size_t)BSs * Mm * 2 * Dd];
__device__ __nv_bfloat16 g_Ky2[(size_t)BSs * Mm * 2 * Dd];
__device__ float g_Vx[(size_t)Bb * Mm * Dd];
__device__ float g_Vy[(size_t)BSs * Mm * Dd];
__device__ float g_part[(size_t)(Bb + BSs) * Mm * 16];   // row-max partials
__device__ unsigned char g_mx[Bb * Mm];
__device__ unsigned char g_my[BSs * Mm];

// ---------------- helpers ------------------------------------------------------
__device__ __forceinline__ float tf32_rna(float a) {
    uint32_t o;
    asm("cvt.rna.tf32.f32 %0, %1;" : "=r"(o) : "f"(a));
    return __uint_as_float(o);
}
__device__ __forceinline__ uint32_t smem_u32(const void* p) {
    uint32_t a;
    asm("{ .reg .u64 t; cvta.to.shared.u64 t, %1; cvt.u32.u64 %0, t; }"
        : "=r"(a) : "l"(p));
    return a;
}
__device__ __forceinline__ void cpa16(uint32_t dst, const void* src) {
    asm volatile("cp.async.cg.shared.global [%0], [%1], 16;"
                 :: "r"(dst), "l"(src) : "memory");
}
__device__ __forceinline__ void sts32(uint32_t addr, float v) {
    asm volatile("st.shared.f32 [%0], %1;" :: "r"(addr), "f"(v) : "memory");
}
__device__ __forceinline__ void ldm_x4(uint32_t* r, uint32_t addr) {
    asm volatile("ldmatrix.sync.aligned.m8n8.x4.shared.b16 {%0,%1,%2,%3}, [%4];"
        : "=r"(r[0]), "=r"(r[1]), "=r"(r[2]), "=r"(r[3]) : "r"(addr));
}
__device__ __forceinline__ void mma_bf16(float* c, const uint32_t* a,
                                         uint32_t b0, uint32_t b1) {
    asm volatile(
        "mma.sync.aligned.m16n8k16.row.col.f32.bf16.bf16.f32 "
        "{%0,%1,%2,%3}, {%4,%5,%6,%7}, {%8,%9}, {%0,%1,%2,%3};"
        : "+f"(c[0]), "+f"(c[1]), "+f"(c[2]), "+f"(c[3])
        : "r"(a[0]), "r"(a[1]), "r"(a[2]), "r"(a[3]), "r"(b0), "r"(b1));
}
__device__ __forceinline__ void mma_tf32(float* c, const uint32_t* a, const uint32_t* b) {
    asm volatile(
        "mma.sync.aligned.m16n8k8.row.col.f32.tf32.tf32.f32 "
        "{%0,%1,%2,%3}, {%4,%5,%6,%7}, {%8,%9}, {%0,%1,%2,%3};"
        : "+f"(c[0]), "+f"(c[1]), "+f"(c[2]), "+f"(c[3])
        : "r"(a[0]), "r"(a[1]), "r"(a[2]), "r"(a[3]), "r"(b[0]), "r"(b[1]));
}

// ============================ fused bf16 NT GEMM path ==========================
__device__ __forceinline__ void issue_stage_f(
    const __nv_bfloat16* __restrict__ A, const __nv_bfloat16* __restrict__ B,
    int c, int nch, uint32_t sb)
{
    if (c < nch) {
        uint32_t sd = sb + (c % DEPTH_BF) * BSTAGE;
        int acol = c * 32;
#pragma unroll
        for (int j = 0; j < 2; j++) {
            int idx = threadIdx.x + 256 * j;
            int row = idx >> 2, slot = idx & 3;
            int g = slot ^ ((row >> 1) & 3);
            uint32_t so = row * 64 + slot * 16;
            const __nv_bfloat16* ap = A + (size_t)row * 512 + acol + g * 8;
            const __nv_bfloat16* bp = B + (size_t)row * 512 + acol + g * 8;
            cpa16(sd + so, ap);
            cpa16(sd + TSZ + so, ap + 256);
            cpa16(sd + 2 * TSZ + so, bp);
            cpa16(sd + 3 * TSZ + so, bp + 256);
        }
    }
    asm volatile("cp.async.commit_group;" ::: "memory");
}

__device__ __forceinline__ void compute_chunk_f(
    uint32_t sd, float (&acc)[4][4][4], int wm, int wn, int lane)
{
    int j = lane >> 3, rin = lane & 7;
    int jk = j >> 1, jo = (j & 1) * 8;
    int rowA = wm * 64 + jo + rin;
    int rowB = wn * 32 + jo + rin;
    int swA = (rowA >> 1) & 3, swB = (rowB >> 1) & 3;
#pragma unroll
    for (int ks = 0; ks < 2; ks++) {
        uint32_t slA = (uint32_t)(((ks * 2 + jk) ^ swA) * 16);
        uint32_t slB = (uint32_t)(((ks * 2 + jk) ^ swB) * 16);
        uint32_t bhi[2][4], blo[2][4];
#pragma unroll
        for (int np = 0; np < 2; np++) {
            ldm_x4(bhi[np], sd + 2 * TSZ + (rowB + np * 16) * 64 + slB);
            ldm_x4(blo[np], sd + 3 * TSZ + (rowB + np * 16) * 64 + slB);
        }
#pragma unroll
        for (int mt = 0; mt < 4; mt++) {
            uint32_t ahi[4], alo[4];
            ldm_x4(ahi, sd + (rowA + mt * 16) * 64 + slA);
            ldm_x4(alo, sd + TSZ + (rowA + mt * 16) * 64 + slA);
#pragma unroll
            for (int nt = 0; nt < 4; nt++) {
                uint32_t b0 = bhi[nt >> 1][nt & 1], b1 = bhi[nt >> 1][(nt & 1) + 2];
                mma_bf16(acc[mt][nt], ahi, b0, b1);
                mma_bf16(acc[mt][nt], alo, b0, b1);
                mma_bf16(acc[mt][nt], ahi,
                         blo[nt >> 1][nt & 1], blo[nt >> 1][(nt & 1) + 2]);
            }
        }
    }
}

__device__ __forceinline__ void gemm_bf16(
    const __nv_bfloat16* __restrict__ A, const __nv_bfloat16* __restrict__ B,
    float (&acc)[4][4][4], uint32_t sb, int wm, int wn, int lane)
{
    constexpr int nch = 8;
#pragma unroll
    for (int s = 0; s < DEPTH_BF - 1; s++)
        issue_stage_f(A, B, s, nch, sb);
#pragma unroll
    for (int c = 0; c < nch; c++) {
        asm volatile("cp.async.wait_group 1;" ::: "memory");
        __syncthreads();
        issue_stage_f(A, B, c + DEPTH_BF - 1, nch, sb);
        compute_chunk_f(sb + (c % DEPTH_BF) * BSTAGE, acc, wm, wn, lane);
    }
}

#define BF16_SETUP()                                        \
    extern __shared__ char smem[];                          \
    uint32_t sb = smem_u32(smem);                           \
    int wid = threadIdx.x >> 5, lane = threadIdx.x & 31;    \
    int wm = wid >> 2, wn = wid & 3;                        \
    int gr = lane >> 2, kc = lane & 3;                      \
    float acc[4][4][4];                                     \
    _Pragma("unroll") for (int i = 0; i < 4; i++)           \
    _Pragma("unroll") for (int jj = 0; jj < 4; jj++)        \
    _Pragma("unroll") for (int q = 0; q < 4; q++) acc[i][jj][q] = 0.f;

// ============================ fp32 NN path (ctx only) ==========================
__device__ __forceinline__ void issue_stage_nnB(
    const float* __restrict__ B, int ldb, int c, int nch, uint32_t bsb)
{
    if (c < nch) {
        int buf = c & (DEPTH_NN - 1);
        uint32_t bd = bsb + buf * (BSTG_NN * 4);
#pragma unroll
        for (int j = 0; j < 2; j++) {
            int idx = threadIdx.x + 256 * j;
            int row = idx >> 5, seg = idx & 31;
            cpa16(bd + (row * BNNP + seg * 4) * 4,
                  B + (size_t)(c * BK32 + row) * ldb + seg * 4);
        }
    }
    asm volatile("cp.async.commit_group;" ::: "memory");
}

__device__ __forceinline__ void compute_chunk_nn(
    const float* __restrict__ As, const float* __restrict__ Bs,
    float (&acc)[4][4][4], int wm, int wn, int gr, int kc)
{
    const int slot4 = (kc ^ (gr & 3)) * 4;
    uint32_t a[2][4][4], b[2][4][2];
#pragma unroll
    for (int mt = 0; mt < 4; mt++) {
        int r0 = wm * 64 + mt * 16 + gr;
        float4 u = *(const float4*)(As + r0 * BK32 + slot4);
        float4 w = *(const float4*)(As + (r0 + 8) * BK32 + slot4);
        a[0][mt][0] = __float_as_uint(u.x); a[0][mt][1] = __float_as_uint(w.x);
        a[0][mt][2] = __float_as_uint(u.y); a[0][mt][3] = __float_as_uint(w.y);
        a[1][mt][0] = __float_as_uint(u.z); a[1][mt][1] = __float_as_uint(w.z);
        a[1][mt][2] = __float_as_uint(u.w); a[1][mt][3] = __float_as_uint(w.w);
    }
#pragma unroll
    for (int k8 = 0; k8 < 2; k8++)
#pragma unroll
        for (int nt = 0; nt < 4; nt++) {
            const float* p = Bs + (k8 * 8 + kc) * BNNP + wn * 32 + nt * 8 + gr;
            b[k8][nt][0] = __float_as_uint(p[0]);
            b[k8][nt][1] = __float_as_uint(p[4 * BNNP]);
        }
#pragma unroll
    for (int k8 = 0; k8 < 2; k8++)
#pragma unroll
        for (int mt = 0; mt < 4; mt++)
#pragma unroll
            for (int nt = 0; nt < 4; nt++)
                mma_tf32(acc[mt][nt], a[k8][mt], b[k8][nt]);
}

// ---------------- fused split + mask norm + y_len -------------------------------
// blocks [0, NSPLIT): elementwise split; NSPLIT -> norm mask_x; NSPLIT+1 -> norm
// mask_y + ylen.
constexpr size_t NXs = (size_t)Bb * Mm * Dd;
constexpr size_t NYs = (size_t)BSs * Mm * Dd;
constexpr size_t NWs = (size_t)Dd * Dd;
constexpr unsigned NSPLIT = (unsigned)((NXs + NYs + 3 * NWs + 255) / 256);

__global__ void split_norm(const float* __restrict__ x, const float* __restrict__ y,
                           const float* __restrict__ Wq, const float* __restrict__ Wk,
                           const float* __restrict__ Wv,
                           const unsigned int* __restrict__ mx_in,
                           const unsigned int* __restrict__ my_in,
                           float* __restrict__ ylen_out)
{
    if (blockIdx.x >= NSPLIT) {
        int which = blockIdx.x - NSPLIT;
        const unsigned int* in = (which == 0) ? mx_in : my_in;
        unsigned char* out = (which == 0) ? g_mx : g_my;
        int n = (which == 0) ? Bb * Mm : BSs * Mm;

        __shared__ int s_flag;
        if (threadIdx.x == 0) s_flag = 0;
        __syncthreads();
        int local = 0;
        for (int i = threadIdx.x; i < n / 4; i += blockDim.x)
            if (in[i] > 1u) local = 1;
        if (local) atomicOr(&s_flag, 1);
        __syncthreads();
        bool byte_packed = (s_flag != 0);
        const unsigned char* inb = (const unsigned char*)in;
        for (int i = threadIdx.x; i < n; i += blockDim.x)
            out[i] = byte_packed ? (inb[i] != 0 ? 1 : 0) : (in[i] != 0u ? 1 : 0);
        if (which == 1) {
            __syncthreads();
            int t = threadIdx.x;
            if (t < 64) {
                int s = t & 7;
                int sum = 0;
                for (int jq = 0; jq < Mm; jq++) sum += g_my[s * Mm + jq] ? 1 : 0;
                ylen_out[t] = (float)sum;
            }
        }
        return;
    }

    size_t i = (size_t)blockIdx.x * blockDim.x + threadIdx.x;
    if (i < NXs) {
        int r = (int)(i / Dd), c = (int)(i % Dd);
        float v = x[i];
        __nv_bfloat16 h = __float2bfloat16(v);
        g_x2[(size_t)r * 512 + c] = h;
        g_x2[(size_t)r * 512 + 256 + c] = __float2bfloat16(v - __bfloat162float(h));
    } else if (i < NXs + NYs) {
        size_t e = i - NXs;
        int r = (int)(e / Dd), c = (int)(e % Dd);
        float v = y[e];
        __nv_bfloat16 h = __float2bfloat16(v);
        g_y2[(size_t)r * 512 + c] = h;
        g_y2[(size_t)r * 512 + 256 + c] = __float2bfloat16(v - __bfloat162float(h));
    } else if (i < NXs + NYs + 3 * NWs) {
        size_t j = i - NXs - NYs;
        int w = (int)(j / NWs);
        size_t e = j % NWs;
        int r = (int)(e / Dd), c = (int)(e % Dd);
        const float* W = (w == 0) ? Wq : (w == 1) ? Wk : Wv;
        float v = W[e];
        __nv_bfloat16 h = __float2bfloat16(v);
        g_W2[w][(size_t)r * 512 + c] = h;
        g_W2[w][(size_t)r * 512 + 256 + c] = __float2bfloat16(v - __bfloat162float(h));
    }
}

// ---------------- projections (fused 3-term bf16) -------------------------------
__global__ __launch_bounds__(256, 2) void proj_kernel()
{
    bool isY = blockIdx.y >= 256;
    int mat = blockIdx.z;
    const __nv_bfloat16* A2 = isY ? g_y2 : g_x2;
    const __nv_bfloat16* B2 = g_W2[mat];
    int row0 = (isY ? (blockIdx.y - 256) : blockIdx.y) * 128;
    int col0 = blockIdx.x * 128;

    BF16_SETUP();
    gemm_bf16(A2 + (size_t)row0 * 512, B2 + (size_t)col0 * 512,
              acc, sb, wm, wn, lane);

    if (mat < 2) {
        __nv_bfloat16* Q2 = (mat == 0) ? (isY ? g_Qy2 : g_Qx2) : (isY ? g_Ky2 : g_Kx2);
#pragma unroll
        for (int mt = 0; mt < 4; mt++) {
            int r = row0 + wm * 64 + mt * 16 + gr;
#pragma unroll
            for (int nt = 0; nt < 4; nt++) {
                int c = col0 + wn * 32 + nt * 8 + kc * 2;
#pragma unroll
                for (int h2 = 0; h2 < 2; h2++) {
                    int rr = r + h2 * 8;
                    float v0 = acc[mt][nt][h2 * 2], v1 = acc[mt][nt][h2 * 2 + 1];
                    __nv_bfloat16 h0 = __float2bfloat16(v0);
                    __nv_bfloat16 h1 = __float2bfloat16(v1);
                    __nv_bfloat162 hi; hi.x = h0; hi.y = h1;
                    __nv_bfloat162 lo;
                    lo.x = __float2bfloat16(v0 - __bfloat162float(h0));
                    lo.y = __float2bfloat16(v1 - __bfloat162float(h1));
                    *(__nv_bfloat162*)(Q2 + (size_t)rr * 512 + c) = hi;
                    *(__nv_bfloat162*)(Q2 + (size_t)rr * 512 + 256 + c) = lo;
                }
            }
        }
    } else {
        float* V = isY ? g_Vy : g_Vx;
#pragma unroll
        for (int mt = 0; mt < 4; mt++) {
            int r = row0 + wm * 64 + mt * 16 + gr;
#pragma unroll
            for (int nt = 0; nt < 4; nt++) {
                int c = col0 + wn * 32 + nt * 8 + kc * 2;
#pragma unroll
                for (int h2 = 0; h2 < 2; h2++) {
                    int rr = r + h2 * 8;
                    *(float2*)(V + (size_t)rr * Dd + c) =
                        make_float2(tf32_rna(acc[mt][nt][h2 * 2]),
                                    tf32_rna(acc[mt][nt][h2 * 2 + 1]));
                }
            }
        }
    }
}

// ---------------- ALL masked score GEMMs + row-max partials ---------------------
__global__ __launch_bounds__(256, 2) void scores_all(
    float* __restrict__ sx, float* __restrict__ sy,
    float* __restrict__ pxy, float* __restrict__ mxy)
{
    int z = blockIdx.z;
    const __nv_bfloat16 *A, *Bp;
    const unsigned char *mr, *mc;
    float* C;
    float* Mx = nullptr;
    int bz = -1;
    if (z < 64) {
        A = g_Qx2 + (size_t)z * Mm * 512; Bp = g_Kx2 + (size_t)z * Mm * 512;
        mr = g_mx + z * Mm; mc = mr;
        C = sx + (size_t)z * Mm * Mm;
        bz = z;
    } else if (z < 128) {
        int zb = z - 64;
        int n = zb >> 3, s = zb & 7, b = s * 8 + n;
        A = g_Qx2 + (size_t)b * Mm * 512; Bp = g_Ky2 + (size_t)s * Mm * 512;
        mr = g_mx + b * Mm; mc = g_my + s * Mm;
        C = pxy + (size_t)zb * Mm * Mm;
        Mx = mxy + (size_t)zb * Mm * Mm;
    } else {
        int zb = z - 128;
        A = g_Qy2 + (size_t)zb * Mm * 512; Bp = g_Ky2 + (size_t)zb * Mm * 512;
        mr = g_my + zb * Mm; mc = mr;
        C = sy + (size_t)zb * Mm * Mm;
        bz = 64 + zb;
    }
    int row0 = blockIdx.y * 128, col0 = blockIdx.x * 128;

    BF16_SETUP();
    gemm_bf16(A + (size_t)row0 * 512, Bp + (size_t)col0 * 512,
              acc, sb, wm, wn, lane);

#pragma unroll
    for (int mt = 0; mt < 4; mt++) {
        int r = row0 + wm * 64 + mt * 16 + gr;
        bool rm0 = mr[r] != 0, rm1 = mr[r + 8] != 0;
        float rx0 = NEG_FILL_F, rx1 = NEG_FILL_F;
#pragma unroll
        for (int nt = 0; nt < 4; nt++) {
            int c = col0 + wn * 32 + nt * 8 + kc * 2;
            bool c0 = mc[c] != 0, c1 = mc[c + 1] != 0;
            bool m00 = rm0 && c0, m01 = rm0 && c1;
            bool m10 = rm1 && c0, m11 = rm1 && c1;
            float2 v0, v1;
            v0.x = m00 ? acc[mt][nt][0] : NEG_FILL_F;
            v0.y = m01 ? acc[mt][nt][1] : NEG_FILL_F;
            v1.x = m10 ? acc[mt][nt][2] : NEG_FILL_F;
            v1.y = m11 ? acc[mt][nt][3] : NEG_FILL_F;
            rx0 = fmaxf(rx0, fmaxf(v0.x, v0.y));
            rx1 = fmaxf(rx1, fmaxf(v1.x, v1.y));
            *(float2*)(C + (size_t)r * Mm + c) = v0;
            *(float2*)(C + (size_t)(r + 8) * Mm + c) = v1;
            if (Mx) {
                *(float2*)(Mx + (size_t)r * Mm + c) =
                    make_float2(m00 ? 1.f : 0.f, m01 ? 1.f : 0.f);
                *(float2*)(Mx + (size_t)(r + 8) * Mm + c) =
                    make_float2(m10 ? 1.f : 0.f, m11 ? 1.f : 0.f);
            }
        }
        if (bz >= 0) {
            rx0 = fmaxf(rx0, __shfl_xor_sync(0xffffffffu, rx0, 1));
            rx0 = fmaxf(rx0, __shfl_xor_sync(0xffffffffu, rx0, 2));
            rx1 = fmaxf(rx1, __shfl_xor_sync(0xffffffffu, rx1, 1));
            rx1 = fmaxf(rx1, __shfl_xor_sync(0xffffffffu, rx1, 2));
            if (kc == 0) {
                float* part = g_part + (size_t)bz * Mm * 16;
                int tcol = blockIdx.x * 4 + wn;
                part[(size_t)r * 16 + tcol] = rx0;
                part[(size_t)(r + 8) * 16 + tcol] = rx1;
            }
        }
    }
}

// ---------------- fused softmax+context AND pxy-softmax in one launch ------------
// z in [0,72): ctx tiles. z in [72, 72+2048): pxy softmax; each (z,y,x) block
// handles 2 rows: rowpair = ((z-72)*8 + y*2 + x).
__global__ __launch_bounds__(256, 2) void ctx_sm_all(
    const float* __restrict__ sx, const float* __restrict__ sy,
    float* __restrict__ out_x, float* __restrict__ out_y,
    float* __restrict__ pxy)
{
    int z = blockIdx.z;
    if (z >= 72) {
        // ---- pxy softmax path: 2 rows per block, 128 threads per row ----
        __shared__ float red1[2][4], red2[2][4];
        int rp = (z - 72) * 8 + blockIdx.y * 2 + blockIdx.x;   // 0..16383
        int half = threadIdx.x >> 7;
        int t = threadIdx.x & 127;
        int w4 = (threadIdx.x >> 5) & 3;
        float4* p = (float4*)(pxy + ((size_t)rp * 2 + half) * Mm);
        float4 v = p[t];
        float m = fmaxf(fmaxf(v.x, v.y), fmaxf(v.z, v.w));
#pragma unroll
        for (int off = 16; off; off >>= 1)
            m = fmaxf(m, __shfl_xor_sync(0xffffffffu, m, off));
        if ((t & 31) == 0) red1[half][w4] = m;
        __syncthreads();
        float bm = fmaxf(fmaxf(red1[half][0], red1[half][1]),
                         fmaxf(red1[half][2], red1[half][3]));
        float4 e;
        e.x = __expf(v.x - bm); e.y = __expf(v.y - bm);
        e.z = __expf(v.z - bm); e.w = __expf(v.w - bm);
        float s = (e.x + e.y) + (e.z + e.w);
#pragma unroll
        for (int off = 16; off; off >>= 1)
            s += __shfl_xor_sync(0xffffffffu, s, off);
        if ((t & 31) == 0) red2[half][w4] = s;
        __syncthreads();
        float inv = 1.0f / ((red2[half][0] + red2[half][1]) +
                            (red2[half][2] + red2[half][3]));
        e.x *= inv; e.y *= inv; e.z *= inv; e.w *= inv;
        p[t] = e;
        return;
    }

    // ---- ctx path ----
    extern __shared__ char smemc[];
    float* As = (float*)smemc;
    float* Bs = As + DEPTH_NN * ASTG32;
    __shared__ float sMax[128], sInv[128];

    int which = (z >= 64) ? 1 : 0;
    int b = which ? (z - 64) : z;
    const float* S = (which ? sy : sx) + (size_t)b * Mm * Mm;
    const float* V = (which ? g_Vy : g_Vx) + (size_t)b * Mm * Dd;
    float* out = which ? out_y : out_x;
    int row0 = blockIdx.y * 128, col0 = blockIdx.x * 128;
    int bz = which ? 64 + b : b;

    if (threadIdx.x < 128) {
        int r = row0 + threadIdx.x;
        const float* part = g_part + ((size_t)bz * Mm + r) * 16;
        float m = NEG_FILL_F;
#pragma unroll
        for (int t = 0; t < 16; t++) m = fmaxf(m, part[t]);
        sMax[threadIdx.x] = m;
    }

    int wid = threadIdx.x >> 5, lane = threadIdx.x & 31;
    int wm = wid >> 2, wn = wid & 3;
    int gr = lane >> 2, kc = lane & 3;
    float acc[4][4][4];
#pragma unroll
    for (int i = 0; i < 4; i++)
#pragma unroll
        for (int j = 0; j < 4; j++)
#pragma unroll
            for (int q = 0; q < 4; q++) acc[i][j][q] = 0.f;

    int rowA0 = threadIdx.x >> 2;
    int g = threadIdx.x & 3;
    const float* Ap0 = S + (size_t)(row0 + rowA0) * Mm + g * 4;
    const float* Ap1 = S + (size_t)(row0 + rowA0 + 64) * Mm + g * 4;
    const float* Bp = V + col0;
    uint32_t asb = smem_u32(As), bsb = smem_u32(Bs);
    uint32_t abase0 = asb + rowA0 * 64 + g * 4;
    uint32_t abase1 = asb + (rowA0 + 64) * 64 + g * 4;
    int sw0 = rowA0 & 3, sw1 = (rowA0 + 64) & 3;

    __syncthreads();
    float mx0 = sMax[rowA0], mx1 = sMax[rowA0 + 64];
    float sum0 = 0.f, sum1 = 0.f;

    constexpr int nch = Mm / BK32;
    float4 cu0 = *(const float4*)(Ap0);
    float4 cu1 = *(const float4*)(Ap1);
#pragma unroll
    for (int s = 0; s < DEPTH_NN - 1; s++)
        issue_stage_nnB(Bp, Dd, s, nch, bsb);

    for (int c = 0; c < nch; c++) {
        float4 nx0, nx1;
        if (c + 1 < nch) {
            nx0 = *(const float4*)(Ap0 + (c + 1) * BK32);
            nx1 = *(const float4*)(Ap1 + (c + 1) * BK32);
        }
        {
            uint32_t bufo = (uint32_t)((c & (DEPTH_NN - 1)) * (ASTG32 * 4));
            float p0[4] = {cu0.x, cu0.y, cu0.z, cu0.w};
            float p1[4] = {cu1.x, cu1.y, cu1.z, cu1.w};
#pragma unroll
            for (int t = 0; t < 4; t++) {
                float e0 = __expf(p0[t] - mx0);
                float e1 = __expf(p1[t] - mx1);
                sum0 += e0; sum1 += e1;
                sts32(abase0 + bufo + (uint32_t)((t ^ sw0) * 16), tf32_rna(e0));
                sts32(abase1 + bufo + (uint32_t)((t ^ sw1) * 16), tf32_rna(e1));
            }
        }
        asm volatile("cp.async.wait_group 2;" ::: "memory");
        __syncthreads();
        issue_stage_nnB(Bp, Dd, c + DEPTH_NN - 1, nch, bsb);
        int buf = c & (DEPTH_NN - 1);
        compute_chunk_nn(As + buf * ASTG32, Bs + buf * BSTG_NN, acc, wm, wn, gr, kc);
        cu0 = nx0; cu1 = nx1;
    }

    sum0 += __shfl_xor_sync(0xffffffffu, sum0, 1);
    sum0 += __shfl_xor_sync(0xffffffffu, sum0, 2);
    sum1 += __shfl_xor_sync(0xffffffffu, sum1, 1);
    sum1 += __shfl_xor_sync(0xffffffffu, sum1, 2);
    __syncthreads();
    if (g == 0) {
        sInv[rowA0] = 1.0f / sum0;
        sInv[rowA0 + 64] = 1.0f / sum1;
    }
    __syncthreads();

    float* O = out + (size_t)b * Mm * Dd;
#pragma unroll
    for (int mt = 0; mt < 4; mt++) {
        int rl = wm * 64 + mt * 16 + gr;
        int r = row0 + rl;
        float i0 = sInv[rl], i1 = sInv[rl + 8];
#pragma unroll
        for (int nt = 0; nt < 4; nt++) {
            int c = col0 + wn * 32 + nt * 8 + kc * 2;
            *(float2*)(O + (size_t)r * Dd + c) =
                make_float2(acc[mt][nt][0] * i0, acc[mt][nt][1] * i0);
            *(float2*)(O + (size_t)(r + 8) * Dd + c) =
                make_float2(acc[mt][nt][2] * i1, acc[mt][nt][3] * i1);
        }
    }
}

// ---------------- launch --------------------------------------------------------------
extern "C" void kernel_launch(void* const* d_in, const int* in_sizes, int n_in,
                              void* d_out, int out_size)
{
    const float* x  = (const float*)d_in[0];
    const float* y  = (const float*)d_in[1];
    const unsigned int* mask_x = (const unsigned int*)d_in[2];
    const unsigned int* mask_y = (const unsigned int*)d_in[3];
    const float* Wq = (const float*)d_in[4];
    const float* Wk = (const float*)d_in[5];
    const float* Wv = (const float*)d_in[6];

    float* out = (float*)d_out;
    float* out_ctx_x = out;                    // 64*512*256
    float* out_ctx_y = out + 8388608;          // 8*512*256
    float* out_sx    = out + 9437184;          // 64*512*512
    float* out_sy    = out + 26214400;         // 8*512*512
    float* out_pxy   = out + 28311552;         // 64*512*512
    float* out_mxy   = out + 45088768;         // 64*512*512
    float* out_ylen  = out + 61865984;         // 64

    cudaFuncSetAttribute(proj_kernel, cudaFuncAttributeMaxDynamicSharedMemorySize, DSMEM_BF);
    cudaFuncSetAttribute(scores_all, cudaFuncAttributeMaxDynamicSharedMemorySize, DSMEM_BF);
    cudaFuncSetAttribute(ctx_sm_all, cudaFuncAttributeMaxDynamicSharedMemorySize, DSMEM_NN);

    dim3 blk(256);

    split_norm<<<NSPLIT + 2, blk>>>(x, y, Wq, Wk, Wv, mask_x, mask_y, out_ylen); // 1
    proj_kernel<<<dim3(2, 288, 3), blk, DSMEM_BF>>>();                           // 2
    scores_all<<<dim3(4, 4, 136), blk, DSMEM_BF>>>(out_sx, out_sy,
                                                   out_pxy, out_mxy);            // 3
    ctx_sm_all<<<dim3(2, 4, 72 + 2048), blk, DSMEM_NN>>>(out_sx, out_sy,
                                                         out_ctx_x, out_ctx_y,
                                                         out_pxy);               // 4
}